// round 1
// baseline (speedup 1.0000x reference)
#include <cuda_runtime.h>

// Problem constants
#define NSRC 20000
#define NTAR 20000

// Main kernel decomposition
#define GRID     148                       // one persistent block per SM
#define NTHREADS 256                       // 8 warps = 2 per SMSP
#define CHUNK    1250                      // src points per shared tile (20 KB)
#define NCHUNK   16                        // NSRC / CHUNK
#define NGROUP   79                        // ceil(NTAR / NTHREADS)
#define NTAR_PAD (NGROUP * NTHREADS)       // 20224
#define NUNITS   (NGROUP * NCHUNK)         // 1264 work units

// Scratch (no cudaMalloc allowed — device globals)
__device__ float4 g_src4[NSRC];                 // {x, y, z, ||s||^2}
__device__ float  g_pm[NCHUNK * NTAR_PAD];      // partial mins per (chunk, target)
__device__ float  g_gsum[NGROUP];               // per-group partial sums

// Kernel 1: precompute src point + squared norm as float4 for LDS.128 loads
__global__ void prep_kernel(const float* __restrict__ src) {
    int i = blockIdx.x * blockDim.x + threadIdx.x;
    if (i < NSRC) {
        float x = src[3 * i + 0];
        float y = src[3 * i + 1];
        float z = src[3 * i + 2];
        g_src4[i] = make_float4(x, y, z, x * x + y * y + z * z);
    }
}

// Kernel 2: main pairwise min. Work unit = (256-target group, 1250-src chunk).
// v = ||s||^2 - 2 s.t  (per-target constant ||t||^2 added in finish kernel)
__global__ __launch_bounds__(NTHREADS, 1) void nn_kernel(const float* __restrict__ tar) {
    __shared__ float4 sh[CHUNK];

    for (int u = blockIdx.x; u < NUNITS; u += GRID) {
        int g = u / NCHUNK;   // target group
        int c = u % NCHUNK;   // src chunk

        int tg = g * NTHREADS + threadIdx.x;
        float tx2 = 0.f, ty2 = 0.f, tz2 = 0.f;
        if (tg < NTAR) {
            tx2 = -2.f * tar[3 * tg + 0];
            ty2 = -2.f * tar[3 * tg + 1];
            tz2 = -2.f * tar[3 * tg + 2];
        }

        // Guard shared-tile reuse from the previous unit, then load tile.
        __syncthreads();
        for (int j = threadIdx.x; j < CHUNK; j += NTHREADS)
            sh[j] = g_src4[c * CHUNK + j];
        __syncthreads();

        float m = 3.402823466e38f;
        #pragma unroll 10
        for (int j = 0; j < CHUNK; j++) {
            float4 s = sh[j];                    // LDS.128, warp-broadcast
            float v = fmaf(s.x, tx2, s.w);
            v = fmaf(s.y, ty2, v);
            v = fmaf(s.z, tz2, v);
            m = fminf(m, v);
        }

        g_pm[c * NTAR_PAD + g * NTHREADS + threadIdx.x] = m;
    }
}

// Kernel 3: per-target min across the 16 chunks, add ||t||^2, block-reduce.
__global__ __launch_bounds__(NTHREADS) void finish_kernel(const float* __restrict__ tar) {
    int i = blockIdx.x * NTHREADS + threadIdx.x;
    float contrib = 0.f;
    if (i < NTAR) {
        float m = g_pm[i];
        #pragma unroll
        for (int c = 1; c < NCHUNK; c++)
            m = fminf(m, g_pm[c * NTAR_PAD + i]);
        float x = tar[3 * i + 0];
        float y = tar[3 * i + 1];
        float z = tar[3 * i + 2];
        contrib = m + x * x + y * y + z * z;   // = min ||s - t||^2
    }

    __shared__ float ws[NTHREADS / 32];
    for (int off = 16; off; off >>= 1)
        contrib += __shfl_down_sync(0xffffffffu, contrib, off);
    if ((threadIdx.x & 31) == 0) ws[threadIdx.x >> 5] = contrib;
    __syncthreads();
    if (threadIdx.x < 32) {
        float v = (threadIdx.x < NTHREADS / 32) ? ws[threadIdx.x] : 0.f;
        for (int off = 4; off; off >>= 1)
            v += __shfl_down_sync(0xffffffffu, v, off);
        if (threadIdx.x == 0) g_gsum[blockIdx.x] = v;
    }
}

// Kernel 4: deterministic final reduction of 79 group sums -> scalar out.
__global__ void final_kernel(float* __restrict__ out) {
    float v = (threadIdx.x < NGROUP) ? g_gsum[threadIdx.x] : 0.f;
    for (int off = 16; off; off >>= 1)
        v += __shfl_down_sync(0xffffffffu, v, off);
    __shared__ float ws[4];
    if ((threadIdx.x & 31) == 0) ws[threadIdx.x >> 5] = v;
    __syncthreads();
    if (threadIdx.x == 0)
        out[0] = 0.5f * (ws[0] + ws[1] + ws[2] + ws[3]);
}

extern "C" void kernel_launch(void* const* d_in, const int* in_sizes, int n_in,
                              void* d_out, int out_size) {
    const float* src = (const float*)d_in[0];   // [20000, 3] fp32
    const float* tar = (const float*)d_in[1];   // [20000, 3] fp32
    float* out = (float*)d_out;                 // scalar fp32

    prep_kernel<<<(NSRC + 255) / 256, 256>>>(src);
    nn_kernel<<<GRID, NTHREADS>>>(tar);
    finish_kernel<<<NGROUP, NTHREADS>>>(tar);
    final_kernel<<<1, 128>>>(out);
}

// round 2
// speedup vs baseline: 1.7035x; 1.7035x over previous
#include <cuda_runtime.h>

// Problem constants
#define NSRC 20000
#define NTAR 20000

// Decomposition: each lane owns 4 targets (2 packed f32x2 pairs).
#define GRID      148                      // persistent, one block per SM
#define NTHREADS  256                      // 8 warps = 2 per SMSP
#define TPB       (NTHREADS * 4)           // 1024 targets per group
#define NGROUP    20                       // ceil(20000 / 1024)
#define NTAR_PAD  (NGROUP * TPB)           // 20480
#define CHUNK     250                      // sources per shared tile (8 KB)
#define NCHUNK    80                       // 20000 / 250
#define NUNITS    (NGROUP * NCHUNK)        // 1600 work units
#define FLT_BIG   3.402823466e38f

// Scratch (device globals — no allocation allowed)
__device__ float g_src8[NSRC * 8];             // per src: {x,x,y,y,z,z,w,w}, w=||s||^2
__device__ float g_pm[NCHUNK * NTAR_PAD];      // partial mins per (chunk, target-slot)
__device__ float g_gsum[79];                   // per-block partial sums (finish grid)

// ---- f32x2 packed-math helpers (Blackwell FFMA2) ----
__device__ __forceinline__ unsigned long long pack2(float lo, float hi) {
    unsigned long long r;
    asm("mov.b64 %0, {%1, %2};" : "=l"(r) : "f"(lo), "f"(hi));
    return r;
}
__device__ __forceinline__ unsigned long long fma2(unsigned long long a,
                                                   unsigned long long b,
                                                   unsigned long long c) {
    unsigned long long d;
    asm("fma.rn.f32x2 %0, %1, %2, %3;" : "=l"(d) : "l"(a), "l"(b), "l"(c));
    return d;
}
__device__ __forceinline__ void unpack2(unsigned long long v, float& lo, float& hi) {
    asm("mov.b64 {%0, %1}, %2;" : "=f"(lo), "=f"(hi) : "l"(v));
}

// Kernel 1: build duplicated-packed source array {x,x,y,y,z,z,w,w}
__global__ void prep_kernel(const float* __restrict__ src) {
    int i = blockIdx.x * blockDim.x + threadIdx.x;
    if (i < NSRC) {
        float x = src[3 * i + 0];
        float y = src[3 * i + 1];
        float z = src[3 * i + 2];
        float w = x * x + y * y + z * z;
        float4* p = (float4*)g_src8;
        p[2 * i + 0] = make_float4(x, x, y, y);
        p[2 * i + 1] = make_float4(z, z, w, w);
    }
}

// Kernel 2: packed pairwise min. v = ||s||^2 - 2 s.t  (||t||^2 added in finish).
__global__ __launch_bounds__(NTHREADS, 1) void nn_kernel(const float* __restrict__ tar) {
    __shared__ ulonglong2 sh[2 * CHUNK];   // per src: sh[2j]=(xx,yy), sh[2j+1]=(zz,ww)

    for (int u = blockIdx.x; u < NUNITS; u += GRID) {
        int g = u / NCHUNK;   // target group (1024 targets)
        int c = u % NCHUNK;   // src chunk (250 sources)

        // Load this lane's 4 targets (k-strided for coalescing), times -2.
        float tx[4], ty[4], tz[4];
        #pragma unroll
        for (int k = 0; k < 4; k++) {
            int t = g * TPB + k * NTHREADS + threadIdx.x;
            if (t < NTAR) {
                tx[k] = -2.f * tar[3 * t + 0];
                ty[k] = -2.f * tar[3 * t + 1];
                tz[k] = -2.f * tar[3 * t + 2];
            } else {
                tx[k] = ty[k] = tz[k] = 0.f;
            }
        }
        unsigned long long txab = pack2(tx[0], tx[1]), txcd = pack2(tx[2], tx[3]);
        unsigned long long tyab = pack2(ty[0], ty[1]), tycd = pack2(ty[2], ty[3]);
        unsigned long long tzab = pack2(tz[0], tz[1]), tzcd = pack2(tz[2], tz[3]);

        // Guard smem reuse, then load the 8 KB tile.
        __syncthreads();
        {
            const float4* gs = (const float4*)g_src8 + (size_t)c * (2 * CHUNK);
            float4* shf = (float4*)sh;
            for (int j = threadIdx.x; j < 2 * CHUNK; j += NTHREADS)
                shf[j] = gs[j];
        }
        __syncthreads();

        float m0 = FLT_BIG, m1 = FLT_BIG, m2 = FLT_BIG, m3 = FLT_BIG;
        #pragma unroll 5
        for (int j = 0; j < CHUNK; j++) {
            ulonglong2 q = sh[2 * j];       // (x,x), (y,y)
            ulonglong2 r = sh[2 * j + 1];   // (z,z), (w,w)
            unsigned long long vab = fma2(q.x, txab, r.y);
            unsigned long long vcd = fma2(q.x, txcd, r.y);
            vab = fma2(q.y, tyab, vab);
            vcd = fma2(q.y, tycd, vcd);
            vab = fma2(r.x, tzab, vab);
            vcd = fma2(r.x, tzcd, vcd);
            float a, b, cc, d;
            unpack2(vab, a, b);
            unpack2(vcd, cc, d);
            m0 = fminf(m0, a);
            m1 = fminf(m1, b);
            m2 = fminf(m2, cc);
            m3 = fminf(m3, d);
        }

        float* row = g_pm + (size_t)c * NTAR_PAD + g * TPB + threadIdx.x;
        row[0 * NTHREADS] = m0;
        row[1 * NTHREADS] = m1;
        row[2 * NTHREADS] = m2;
        row[3 * NTHREADS] = m3;
    }
}

// Kernel 3: min across 80 chunks, add ||t||^2, block-reduce (slot index == target index).
__global__ __launch_bounds__(NTHREADS) void finish_kernel(const float* __restrict__ tar) {
    int i = blockIdx.x * NTHREADS + threadIdx.x;
    float contrib = 0.f;
    if (i < NTAR) {
        float m = g_pm[i];
        #pragma unroll
        for (int c = 1; c < NCHUNK; c++)
            m = fminf(m, g_pm[(size_t)c * NTAR_PAD + i]);
        float x = tar[3 * i + 0];
        float y = tar[3 * i + 1];
        float z = tar[3 * i + 2];
        contrib = m + x * x + y * y + z * z;   // = min ||s - t||^2
    }

    __shared__ float ws[NTHREADS / 32];
    for (int off = 16; off; off >>= 1)
        contrib += __shfl_down_sync(0xffffffffu, contrib, off);
    if ((threadIdx.x & 31) == 0) ws[threadIdx.x >> 5] = contrib;
    __syncthreads();
    if (threadIdx.x < 32) {
        float v = (threadIdx.x < NTHREADS / 32) ? ws[threadIdx.x] : 0.f;
        for (int off = 4; off; off >>= 1)
            v += __shfl_down_sync(0xffffffffu, v, off);
        if (threadIdx.x == 0) g_gsum[blockIdx.x] = v;
    }
}

// Kernel 4: deterministic final reduction of 79 block sums -> scalar.
__global__ void final_kernel(float* __restrict__ out) {
    float v = (threadIdx.x < 79) ? g_gsum[threadIdx.x] : 0.f;
    for (int off = 16; off; off >>= 1)
        v += __shfl_down_sync(0xffffffffu, v, off);
    __shared__ float ws[4];
    if ((threadIdx.x & 31) == 0) ws[threadIdx.x >> 5] = v;
    __syncthreads();
    if (threadIdx.x == 0)
        out[0] = 0.5f * (ws[0] + ws[1] + ws[2] + ws[3]);
}

extern "C" void kernel_launch(void* const* d_in, const int* in_sizes, int n_in,
                              void* d_out, int out_size) {
    const float* src = (const float*)d_in[0];   // [20000, 3] fp32
    const float* tar = (const float*)d_in[1];   // [20000, 3] fp32
    float* out = (float*)d_out;                 // scalar fp32

    prep_kernel<<<(NSRC + 255) / 256, 256>>>(src);
    nn_kernel<<<GRID, NTHREADS>>>(tar);
    finish_kernel<<<79, NTHREADS>>>(tar);
    final_kernel<<<1, 128>>>(out);
}